// round 5
// baseline (speedup 1.0000x reference)
#include <cuda_runtime.h>

// MultiScaleEdgeBuilder: B=64 graphs, 256 nodes each, all ordered intra-graph
// pairs (i != j). Output (float32, concatenated):
//   [0, 2E)    edge_index  (row indices, then col indices)
//   [2E, 18E)  edge_attr   (zeros, EDGE_DIM=16)
//   [18E, 21E) rbf         exp(-d^2 / c^2), c in {4, 8, 12}
// E = 64 * 256 * 255 = 4,177,920.
//
// R3: coarsen to 1024 edges/block (4/thread) for larger contiguous DRAM
// chunks per stream, float4 index stores, and __stcs (evict-first) on all
// output stores. Pure HBM-write-bound; target is the write ceiling.

#define NPER    256
#define EPG     (NPER * (NPER - 1))      // 65280 edges per graph
#define E_TOTAL (64 * EPG)               // 4,177,920 = 4080 * 1024
#define EPB     1024                     // edges per block

__global__ __launch_bounds__(256, 8)
void MultiScaleEdgeBuilder_kernel(const float* __restrict__ pos,
                                  float* __restrict__ out) {
    __shared__ __align__(16) float s_rbf[3 * EPB];   // 12 KB

    const int tid = threadIdx.x;
    const int e0  = blockIdx.x * EPB;        // first edge of this block

    float rowv[4], colv[4];

    #pragma unroll
    for (int k = 0; k < 4; k++) {
        int e  = e0 + tid * 4 + k;
        // ---- decompose edge id -> (g, i, j) ----
        int g  = e / EPG;                    // const-div -> mul.hi
        int r  = e - g * EPG;
        int i  = r / 255;
        int jp = r - i * 255;
        int j  = jp + (jp >= i);             // skip diagonal

        int row = (g << 8) + i;
        int col = (g << 8) + j;
        rowv[k] = (float)row;
        colv[k] = (float)col;

        // ---- rbf: exp(-d^2/c^2), no sqrt needed ----
        const float* pr = pos + 3 * row;     // L1/L2 hits (pos = 192 KB)
        const float* pc = pos + 3 * col;
        float dx = pr[0] - pc[0];
        float dy = pr[1] - pc[1];
        float dz = pr[2] - pc[2];
        float d2 = dx * dx + dy * dy + dz * dz;

        int t4 = tid * 4 + k;
        s_rbf[3 * t4 + 0] = __expf(-d2 * (1.0f / 16.0f));    // c = 4
        s_rbf[3 * t4 + 1] = __expf(-d2 * (1.0f / 64.0f));    // c = 8
        s_rbf[3 * t4 + 2] = __expf(-d2 * (1.0f / 144.0f));   // c = 12
    }

    // ---- edge_index: 4 consecutive e per thread -> float4, coalesced ----
    float4* rp4 = (float4*)(out + e0);
    __stcs(&rp4[tid], make_float4(rowv[0], rowv[1], rowv[2], rowv[3]));
    float4* cp4 = (float4*)(out + E_TOTAL + e0);
    __stcs(&cp4[tid], make_float4(colv[0], colv[1], colv[2], colv[3]));

    // ---- zeros: 64 KB contiguous per block = 4096 float4 ----
    {
        float4 z = make_float4(0.f, 0.f, 0.f, 0.f);
        float4* zp = (float4*)(out + 2 * E_TOTAL + 16 * e0);
        #pragma unroll
        for (int k = 0; k < 16; k++)
            __stcs(&zp[tid + 256 * k], z);   // 128B per warp-store
    }

    __syncthreads();

    // ---- rbf: 12 KB contiguous per block, coalesced float4 from smem ----
    {
        const float4* s4 = (const float4*)s_rbf;
        float4* rb = (float4*)(out + 18 * E_TOTAL + 3 * e0);
        #pragma unroll
        for (int k = 0; k < 3; k++)
            __stcs(&rb[tid + 256 * k], s4[tid + 256 * k]);
    }
}

extern "C" void kernel_launch(void* const* d_in, const int* in_sizes, int n_in,
                              void* d_out, int out_size) {
    const float* pos = (const float*)d_in[0];   // [16384, 3] float32
    float* out = (float*)d_out;                 // 21 * E floats

    MultiScaleEdgeBuilder_kernel<<<E_TOTAL / EPB, 256>>>(pos, out);
}

// round 6
// speedup vs baseline: 1.0315x; 1.0315x over previous
#include <cuda_runtime.h>

// MultiScaleEdgeBuilder: B=64 graphs, 256 nodes each, all ordered intra-graph
// pairs (i != j). Output (float32, concatenated):
//   [0, 2E)    edge_index  (row indices, then col indices)
//   [2E, 18E)  edge_attr   (zeros, EDGE_DIM=16)
//   [18E, 21E) rbf         exp(-d^2 / c^2), c in {4, 8, 12}
// E = 64 * 256 * 255 = 4,177,920.
//
// R5: revert to R2 structure (evict-normal stores — the 126MB L2 is a write
// buffer; __stcs in R3 defeated it and regressed). Changes vs R2:
//   - 512-thread blocks / 512 edges per block (fewer blocks & barriers)
//   - zero-fill stores issued FIRST (no deps; hides MUFU latency)

#define NPER    256
#define EPG     (NPER * (NPER - 1))      // 65280 edges per graph
#define E_TOTAL (64 * EPG)               // 4,177,920 = 8160 * 512
#define EPB     512                      // edges per block
#define NTHR    512

__global__ __launch_bounds__(NTHR, 4)
void MultiScaleEdgeBuilder_kernel(const float* __restrict__ pos,
                                  float* __restrict__ out) {
    __shared__ __align__(16) float s_rbf[3 * EPB];   // 6 KB

    const int tid = threadIdx.x;
    const int e0  = blockIdx.x * EPB;        // first edge of this block
    const int e   = e0 + tid;

    // ---- zeros first: 512*16 floats = 2048 float4, contiguous 32 KB -----
    // Pure stores with no dependencies: fills the store pipe while the
    // rbf dependency chain (loads + MUFU) is still in flight.
    {
        float4 z = make_float4(0.f, 0.f, 0.f, 0.f);
        float4* zp = (float4*)(out + 2 * E_TOTAL + 16 * e0);
        #pragma unroll
        for (int k = 0; k < 4; k++)
            zp[tid + NTHR * k] = z;          // coalesced 128B per warp-store
    }

    // ---- decompose edge id -> (g, i, j) ---------------------------------
    int g  = e / EPG;                        // const-div -> mul.hi
    int r  = e - g * EPG;
    int i  = r / 255;
    int jp = r - i * 255;
    int j  = jp + (jp >= i);                 // skip diagonal

    int row = (g << 8) + i;
    int col = (g << 8) + j;

    // ---- edge_index: consecutive e -> perfectly coalesced ---------------
    out[e]           = (float)row;
    out[E_TOTAL + e] = (float)col;

    // ---- rbf: exp(-d^2/c^2), no sqrt needed -----------------------------
    const float* pr = pos + 3 * row;         // warp-mostly-uniform, L1/L2 hit
    const float* pc = pos + 3 * col;
    float dx = pr[0] - pc[0];
    float dy = pr[1] - pc[1];
    float dz = pr[2] - pc[2];
    float d2 = dx * dx + dy * dy + dz * dz;

    s_rbf[3 * tid + 0] = __expf(-d2 * (1.0f / 16.0f));   // c = 4  (stride-3:
    s_rbf[3 * tid + 1] = __expf(-d2 * (1.0f / 64.0f));   //  c = 8  bank-
    s_rbf[3 * tid + 2] = __expf(-d2 * (1.0f / 144.0f));  //  c = 12 conflict-free)

    __syncthreads();

    // ---- rbf out: 1536 floats = 384 float4, coalesced from smem ---------
    if (tid < 384) {
        const float4* s4 = (const float4*)s_rbf;
        float4* rp = (float4*)(out + 18 * E_TOTAL + 3 * e0);
        rp[tid] = s4[tid];
    }
}

extern "C" void kernel_launch(void* const* d_in, const int* in_sizes, int n_in,
                              void* d_out, int out_size) {
    const float* pos = (const float*)d_in[0];   // [16384, 3] float32
    float* out = (float*)d_out;                 // 21 * E floats

    MultiScaleEdgeBuilder_kernel<<<E_TOTAL / EPB, NTHR>>>(pos, out);
}

// round 7
// speedup vs baseline: 1.0322x; 1.0006x over previous
#include <cuda_runtime.h>

// MultiScaleEdgeBuilder: B=64 graphs, 256 nodes each, all ordered intra-graph
// pairs (i != j). Output (float32, concatenated):
//   [0, 2E)    edge_index  (row indices, then col indices)
//   [2E, 18E)  edge_attr   (zeros, EDGE_DIM=16)
//   [18E, 21E) rbf         exp(-d^2 / c^2), c in {4, 8, 12}
// E = 64 * 256 * 255 = 4,177,920.
//
// R6: clean coarsening test — EPB=1024 (2 edges/thread, stride 512), with
// NONE of the R3 confounds: evict-normal stores (L2 is the write buffer),
// stride-3 smem staging (bank-conflict-free). Per-block contiguous chunks
// double to 4KB idx / 4KB idx / 64KB zeros / 12KB rbf.

#define NPER    256
#define EPG     (NPER * (NPER - 1))      // 65280 edges per graph
#define E_TOTAL (64 * EPG)               // 4,177,920 = 4080 * 1024
#define EPB     1024                     // edges per block
#define NTHR    512

__global__ __launch_bounds__(NTHR, 4)
void MultiScaleEdgeBuilder_kernel(const float* __restrict__ pos,
                                  float* __restrict__ out) {
    __shared__ __align__(16) float s_rbf[3 * EPB];   // 12 KB

    const int tid = threadIdx.x;
    const int e0  = blockIdx.x * EPB;        // first edge of this block

    // ---- zeros first: 1024*16 floats = 4096 float4, contiguous 64 KB ----
    // No dependencies: keeps the store pipe busy under the MUFU chain.
    {
        float4 z = make_float4(0.f, 0.f, 0.f, 0.f);
        float4* zp = (float4*)(out + 2 * E_TOTAL + 16 * e0);
        #pragma unroll
        for (int k = 0; k < 8; k++)
            zp[tid + NTHR * k] = z;          // coalesced 128B per warp-store
    }

    // ---- two edges per thread: e0+tid and e0+512+tid ---------------------
    #pragma unroll
    for (int h = 0; h < 2; h++) {
        const int le = tid + NTHR * h;       // local edge id in block
        const int e  = e0 + le;

        // decompose edge id -> (g, i, j)
        int g  = e / EPG;                    // const-div -> mul.hi
        int r  = e - g * EPG;
        int i  = r / 255;
        int jp = r - i * 255;
        int j  = jp + (jp >= i);             // skip diagonal

        int row = (g << 8) + i;
        int col = (g << 8) + j;

        // edge_index: consecutive e across warp -> perfectly coalesced
        out[e]           = (float)row;
        out[E_TOTAL + e] = (float)col;

        // rbf: exp(-d^2/c^2), no sqrt needed
        const float* pr = pos + 3 * row;     // warp-mostly-uniform, L1/L2 hit
        const float* pc = pos + 3 * col;
        float dx = pr[0] - pc[0];
        float dy = pr[1] - pc[1];
        float dz = pr[2] - pc[2];
        float d2 = dx * dx + dy * dy + dz * dz;

        // stride-3 smem writes: gcd(3,32)=1 -> bank-conflict-free
        s_rbf[3 * le + 0] = __expf(-d2 * (1.0f / 16.0f));    // c = 4
        s_rbf[3 * le + 1] = __expf(-d2 * (1.0f / 64.0f));    // c = 8
        s_rbf[3 * le + 2] = __expf(-d2 * (1.0f / 144.0f));   // c = 12
    }

    __syncthreads();

    // ---- rbf out: 3072 floats = 768 float4, coalesced from smem ---------
    {
        const float4* s4 = (const float4*)s_rbf;
        float4* rp = (float4*)(out + 18 * E_TOTAL + 3 * e0);
        rp[tid] = s4[tid];
        if (tid < 256)
            rp[NTHR + tid] = s4[NTHR + tid];
    }
}

extern "C" void kernel_launch(void* const* d_in, const int* in_sizes, int n_in,
                              void* d_out, int out_size) {
    const float* pos = (const float*)d_in[0];   // [16384, 3] float32
    float* out = (float*)d_out;                 // 21 * E floats

    MultiScaleEdgeBuilder_kernel<<<E_TOTAL / EPB, NTHR>>>(pos, out);
}

// round 8
// speedup vs baseline: 1.0328x; 1.0006x over previous
#include <cuda_runtime.h>

// MultiScaleEdgeBuilder: B=64 graphs, 256 nodes each, all ordered intra-graph
// pairs (i != j). Output (float32, concatenated):
//   [0, 2E)    edge_index  (row indices, then col indices)
//   [2E, 18E)  edge_attr   (zeros, EDGE_DIM=16)
//   [18E, 21E) rbf         exp(-d^2 / c^2), c in {4, 8, 12}
// E = 64 * 256 * 255 = 4,177,920.
//
// R7 (final): R5 structure, re-benched for stability. Evidence across R2-R6:
// bench period is pinned at ~51.7us = 351MB / 6.79TB/s = 85% of spec HBM —
// the HBM write ceiling. All stores fully coalesced, full-sector coverage
// (no RFO traffic), evict-normal (L2 acts as write buffer; __stcs regressed).
// No remaining lever: every output byte is mandatory per replay.

#define NPER    256
#define EPG     (NPER * (NPER - 1))      // 65280 edges per graph
#define E_TOTAL (64 * EPG)               // 4,177,920 = 8160 * 512
#define EPB     512                      // edges per block
#define NTHR    512

__global__ __launch_bounds__(NTHR, 4)
void MultiScaleEdgeBuilder_kernel(const float* __restrict__ pos,
                                  float* __restrict__ out) {
    __shared__ __align__(16) float s_rbf[3 * EPB];   // 6 KB

    const int tid = threadIdx.x;
    const int e0  = blockIdx.x * EPB;        // first edge of this block
    const int e   = e0 + tid;

    // ---- zeros first: 512*16 floats = 2048 float4, contiguous 32 KB -----
    // Pure stores with no dependencies: fills the store pipe while the
    // rbf dependency chain (loads + MUFU) is still in flight.
    {
        float4 z = make_float4(0.f, 0.f, 0.f, 0.f);
        float4* zp = (float4*)(out + 2 * E_TOTAL + 16 * e0);
        #pragma unroll
        for (int k = 0; k < 4; k++)
            zp[tid + NTHR * k] = z;          // coalesced 128B per warp-store
    }

    // ---- decompose edge id -> (g, i, j) ---------------------------------
    int g  = e / EPG;                        // const-div -> mul.hi
    int r  = e - g * EPG;
    int i  = r / 255;
    int jp = r - i * 255;
    int j  = jp + (jp >= i);                 // skip diagonal

    int row = (g << 8) + i;
    int col = (g << 8) + j;

    // ---- edge_index: consecutive e -> perfectly coalesced ---------------
    out[e]           = (float)row;
    out[E_TOTAL + e] = (float)col;

    // ---- rbf: exp(-d^2/c^2), no sqrt needed -----------------------------
    const float* pr = pos + 3 * row;         // warp-mostly-uniform, L1/L2 hit
    const float* pc = pos + 3 * col;
    float dx = pr[0] - pc[0];
    float dy = pr[1] - pc[1];
    float dz = pr[2] - pc[2];
    float d2 = dx * dx + dy * dy + dz * dz;

    s_rbf[3 * tid + 0] = __expf(-d2 * (1.0f / 16.0f));   // c = 4  (stride-3:
    s_rbf[3 * tid + 1] = __expf(-d2 * (1.0f / 64.0f));   //  c = 8  bank-
    s_rbf[3 * tid + 2] = __expf(-d2 * (1.0f / 144.0f));  //  c = 12 conflict-free)

    __syncthreads();

    // ---- rbf out: 1536 floats = 384 float4, coalesced from smem ---------
    if (tid < 384) {
        const float4* s4 = (const float4*)s_rbf;
        float4* rp = (float4*)(out + 18 * E_TOTAL + 3 * e0);
        rp[tid] = s4[tid];
    }
}

extern "C" void kernel_launch(void* const* d_in, const int* in_sizes, int n_in,
                              void* d_out, int out_size) {
    const float* pos = (const float*)d_in[0];   // [16384, 3] float32
    float* out = (float*)d_out;                 // 21 * E floats

    MultiScaleEdgeBuilder_kernel<<<E_TOTAL / EPB, NTHR>>>(pos, out);
}